// round 15
// baseline (speedup 1.0000x reference)
#include <cuda_runtime.h>
#include <cuda_fp16.h>
#include <stdint.h>
#include <math.h>

// Problem constants
#define TT   512
#define BB   256
#define IIN  512
#define HH   1024
#define OO   512
#define KF   32

#define SPLIT_SC  4096.0f
#define SPLIT_ISC (1.0f / 4096.0f)

typedef __half fp16;

// -------------------- scratch (static __device__, no allocs) -----------------
__device__ __align__(128) float g_coefA[KF * IIN];
__device__ __align__(128) fp16  g_Uhi[(size_t)TT * BB * IIN];
__device__ __align__(128) float g_A[(size_t)TT * BB * HH];
__device__ __align__(128) fp16  g_Wxhi[HH * IIN];
__device__ __align__(128) fp16  g_Whhi[HH * HH];
__device__ __align__(128) fp16  g_Wohi[OO * HH];
__device__ __align__(128) fp16  g_hhi[2][BB * HH];
__device__ __align__(128) fp16  g_hloT[BB * HH];   // lo of FINAL h only (GEMM3)
__device__ unsigned g_arriveG[8];
__device__ unsigned g_genG[8];

// -------------------- PTX helpers (base sm_100-safe) --------------------------
__device__ __forceinline__ uint32_t smem_to_u32(const void* p) {
    uint32_t a;
    asm("{ .reg .u64 t; cvta.to.shared.u64 t, %1; cvt.u32.u64 %0, t; }"
        : "=r"(a) : "l"(p));
    return a;
}
__device__ __forceinline__ void cpasync16(uint32_t s, const void* g) {
    asm volatile("cp.async.cg.shared.global [%0], [%1], 16;" :: "r"(s), "l"(g));
}
#define CP_COMMIT() asm volatile("cp.async.commit_group;" ::: "memory")
#define CP_WAIT1()  asm volatile("cp.async.wait_group 1;" ::: "memory")
#define CP_WAIT0()  asm volatile("cp.async.wait_group 0;" ::: "memory")

__device__ __forceinline__ void ldsm4(uint32_t* r, uint32_t addr) {
    asm volatile(
        "ldmatrix.sync.aligned.m8n8.x4.shared.b16 {%0,%1,%2,%3}, [%4];"
        : "=r"(r[0]), "=r"(r[1]), "=r"(r[2]), "=r"(r[3]) : "r"(addr));
}
__device__ __forceinline__ void mma16816(float* d, const uint32_t* a,
                                         const uint32_t* b) {
    asm volatile(
        "mma.sync.aligned.m16n8k16.row.col.f32.f16.f16.f32 "
        "{%0,%1,%2,%3}, {%4,%5,%6,%7}, {%8,%9}, {%0,%1,%2,%3};"
        : "+f"(d[0]), "+f"(d[1]), "+f"(d[2]), "+f"(d[3])
        : "r"(a[0]), "r"(a[1]), "r"(a[2]), "r"(a[3]), "r"(b[0]), "r"(b[1]));
}
__device__ __forceinline__ uint32_t pack_half2(float a, float b) {
    fp16 h0 = __float2half_rn(a), h1 = __float2half_rn(b);
    return (uint32_t)__half_as_ushort(h0) |
           ((uint32_t)__half_as_ushort(h1) << 16);
}
__device__ __forceinline__ float tanh_fast(float x) {
    float r;
    asm("tanh.approx.f32 %0, %1;" : "=f"(r) : "f"(x));
    return r;
}

// -------------------- small kernels -------------------------------------------
__global__ void reset_kernel() {
#pragma unroll
    for (int i = 0; i < 8; i++) { g_arriveG[i] = 0u; g_genG[i] = 0u; }
}

__global__ void coef_kernel(const float* __restrict__ b_d, float* __restrict__ coef) {
    int i = blockIdx.x * blockDim.x + threadIdx.x;
    if (i >= IIN) return;
    float d = 0.5f / (1.0f + expf(-b_d[i]));
    float p = 1.0f;
    for (int j = 0; j < KF; j++) {
        p *= ((float)j - d) / ((float)j + 1.0f);
        coef[j * IIN + i] = p;
    }
}

// fused fp32 -> fp16 conversion of all three weight matrices (float2 -> half2)
#define WX_N (HH * IIN)
#define WH_N (HH * HH)
#define WO_N (OO * HH)
__global__ void whalf_all_kernel(const float* __restrict__ W_x,
                                 const float* __restrict__ W_h,
                                 const float* __restrict__ W_o,
                                 fp16* __restrict__ Wxhi,
                                 fp16* __restrict__ Whhi,
                                 fp16* __restrict__ Wohi) {
    int p = blockIdx.x * blockDim.x + threadIdx.x;  // pair index
    int i = p * 2;
    const float* src;
    fp16* dst;
    if (i < WX_N) {
        src = W_x + i; dst = Wxhi + i;
    } else if (i < WX_N + WH_N) {
        src = W_h + (i - WX_N); dst = Whhi + (i - WX_N);
    } else if (i < WX_N + WH_N + WO_N) {
        src = W_o + (i - WX_N - WH_N); dst = Wohi + (i - WX_N - WH_N);
    } else {
        return;
    }
    float2 v = *(const float2*)src;
    *(uint32_t*)dst = pack_half2(v.x, v.y);
}

// U[t,b,i] = x[t,b,i] + sum_{j=1..K} pi_j[i]*x[t-j,b,i]; fp16 hi only.
__global__ void fracconv_kernel(const float* __restrict__ x,
                                const float* __restrict__ coef,
                                fp16* __restrict__ Uhi) {
    int idx = blockIdx.x * blockDim.x + threadIdx.x;  // b*I + i
    int i = idx & (IIN - 1);
    float c[KF];
#pragma unroll
    for (int j = 0; j < KF; j++) c[j] = coef[j * IIN + i];
    float w[KF];
#pragma unroll
    for (int j = 0; j < KF; j++) w[j] = 0.0f;

    const float* xp = x + idx;
    const size_t stride = (size_t)BB * IIN;

    for (int t0 = 0; t0 < TT; t0 += KF) {
#pragma unroll
        for (int tt = 0; tt < KF; tt++) {
            float xt = xp[(size_t)(t0 + tt) * stride];
            float u = xt;
#pragma unroll
            for (int j = 1; j <= KF; j++) u += c[j - 1] * w[(tt - j) & (KF - 1)];
            Uhi[(size_t)(t0 + tt) * stride + idx] = __float2half_rn(u);
            w[tt] = xt;
        }
    }
}

// -------------------- batched mma GEMM (templated K-chunk) --------------------
// Yf = sum_k A*B^T + biasC;  acc(AhBh) [+ scaled corr acc(AlBh) if TWO].
// KCB = K-chunk size in halves; smem rows are (KCB + 8) halves.

template <int BM, int BN, bool TWO, int KCB>
__device__ __forceinline__ void prefetch_chunk(
    uint32_t sb, int stageByte,
    const fp16* gAh, const fp16* gAl, const fp16* gBh, int Kd, int tid) {
    constexpr int ROWB = (KCB + 8) * 2;
    constexpr int UNITS = KCB / 8;            // 16B units per row
    constexpr int OFF_AL = BM * ROWB;
    constexpr int OFF_BH = (TWO ? 2 : 1) * BM * ROWB;
    const size_t rs = (size_t)Kd * 2;
#pragma unroll
    for (int u = tid; u < BM * UNITS; u += 256) {
        int r = u / UNITS, q = u % UNITS;
        uint32_t so = (uint32_t)(r * ROWB + q * 16);
        cpasync16(sb + stageByte + so, (const char*)gAh + (size_t)r * rs + q * 16);
        if (TWO)
            cpasync16(sb + stageByte + OFF_AL + so,
                      (const char*)gAl + (size_t)r * rs + q * 16);
    }
#pragma unroll
    for (int u = tid; u < BN * UNITS; u += 256) {
        int r = u / UNITS, q = u % UNITS;
        uint32_t so = (uint32_t)(r * ROWB + q * 16);
        cpasync16(sb + stageByte + OFF_BH + so, (const char*)gBh + (size_t)r * rs + q * 16);
    }
}

template <int BM, int BN, int WGM, int WGN, bool TWO, int KCB>
__global__ __launch_bounds__(256) void mma_gemm(
    const fp16* __restrict__ Ahi, const fp16* __restrict__ Alo,
    const fp16* __restrict__ Bhi,
    const float* __restrict__ biasC, float* __restrict__ Yf, int Kd, int ldO) {
    static_assert(WGM * WGN == 8, "8 warps");
    constexpr int WM = BM / WGM, WN = BN / WGN;
    constexpr int MT = WM / 16, NT16 = WN / 16;
    constexpr int ROWB = (KCB + 8) * 2;
    constexpr int STAGE = ((TWO ? 2 : 1) * BM + BN) * ROWB;
    constexpr int OFF_AL = BM * ROWB;
    constexpr int OFF_BH = (TWO ? 2 : 1) * BM * ROWB;

    extern __shared__ __align__(16) char smem[];
    const uint32_t sb = smem_to_u32(smem);
    const int tid = threadIdx.x;
    const int wid = tid >> 5, lane = tid & 31;
    const int warpM = wid % WGM, warpN = wid / WGM;
    const int m0 = blockIdx.y * BM;
    const int n0 = blockIdx.x * BN;

    float acc[MT][NT16 * 2][4];
    float accC[TWO ? MT : 1][TWO ? NT16 * 2 : 1][4];
#pragma unroll
    for (int a = 0; a < MT; a++)
#pragma unroll
        for (int b = 0; b < NT16 * 2; b++)
#pragma unroll
            for (int c = 0; c < 4; c++) acc[a][b][c] = 0.0f;
    if (TWO) {
#pragma unroll
        for (int a = 0; a < MT; a++)
#pragma unroll
            for (int b = 0; b < NT16 * 2; b++)
#pragma unroll
                for (int c = 0; c < 4; c++) accC[a][b][c] = 0.0f;
    }

    const fp16* gAh = Ahi + (size_t)m0 * Kd;
    const fp16* gAl = TWO ? (Alo + (size_t)m0 * Kd) : nullptr;
    const fp16* gBh = Bhi + (size_t)n0 * Kd;

    const int nch = Kd / KCB;
    prefetch_chunk<BM, BN, TWO, KCB>(sb, 0, gAh, gAl, gBh, Kd, tid);
    CP_COMMIT();

    const int aRow = warpM * WM + (lane & 15);
    const int aCol = (lane >> 4) * 16;
    const int bRow = warpN * WN + (lane & 7) + ((lane >> 4) << 3);
    const int bCol = ((lane >> 3) & 1) * 16;

    for (int i = 0; i < nch; i++) {
        const int buf = i & 1;
        if (i + 1 < nch) {
            prefetch_chunk<BM, BN, TWO, KCB>(sb, (buf ^ 1) * STAGE,
                                             gAh + (size_t)(i + 1) * KCB,
                                             TWO ? gAl + (size_t)(i + 1) * KCB : nullptr,
                                             gBh + (size_t)(i + 1) * KCB, Kd, tid);
            CP_COMMIT();
            CP_WAIT1();
        } else {
            CP_WAIT0();
        }
        __syncthreads();

        const uint32_t s0 = sb + buf * STAGE;
#pragma unroll
        for (int ks = 0; ks < KCB / 16; ks++) {
            const int kB = ks * 32;
            uint32_t Ah[MT][4], Al[MT][4], Bh[NT16][4];
#pragma unroll
            for (int mt = 0; mt < MT; mt++) {
                uint32_t ad = s0 + (uint32_t)((aRow + mt * 16) * ROWB + kB + aCol);
                ldsm4(Ah[mt], ad);
                if (TWO) ldsm4(Al[mt], ad + OFF_AL);
            }
#pragma unroll
            for (int nt = 0; nt < NT16; nt++) {
                uint32_t bd = s0 + (uint32_t)((bRow + nt * 16) * ROWB + kB + bCol);
                ldsm4(Bh[nt], bd + OFF_BH);
            }
#pragma unroll
            for (int mt = 0; mt < MT; mt++)
#pragma unroll
                for (int nt = 0; nt < NT16; nt++) {
                    mma16816(acc[mt][2 * nt + 0],  Ah[mt], &Bh[nt][0]);
                    mma16816(acc[mt][2 * nt + 1],  Ah[mt], &Bh[nt][2]);
                    if (TWO) {
                        mma16816(accC[mt][2 * nt + 0], Al[mt], &Bh[nt][0]);
                        mma16816(accC[mt][2 * nt + 1], Al[mt], &Bh[nt][2]);
                    }
                }
        }
        __syncthreads();
    }

#pragma unroll
    for (int mt = 0; mt < MT; mt++) {
#pragma unroll
        for (int nt8 = 0; nt8 < NT16 * 2; nt8++) {
            const int m = m0 + warpM * WM + mt * 16 + (lane >> 2);
            const int n = n0 + warpN * WN + nt8 * 8 + 2 * (lane & 3);
#pragma unroll
            for (int half = 0; half < 2; half++) {
                const int mm = m + half * 8;
                const float2 bb = *(const float2*)(biasC + n);
                float v0 = acc[mt][nt8][2 * half + 0] + bb.x;
                float v1 = acc[mt][nt8][2 * half + 1] + bb.y;
                if (TWO) {
                    v0 += accC[mt][nt8][2 * half + 0] * SPLIT_ISC;
                    v1 += accC[mt][nt8][2 * half + 1] * SPLIT_ISC;
                }
                *(float2*)(Yf + (size_t)mm * ldO + n) = make_float2(v0, v1);
            }
        }
    }
}

// -------------------- persistent recurrence kernel ----------------------------
// R13 structure; barrier tweak: the last-arriving CTA (the releaser) skips the
// gen poll, removing one L2 round trip from the critical path each step.
#define PK_CTAS 128
#define PK_KC   512
#define PK_ROWB 1040                          // (512+8) halves, bytes
#define WH_STRIDE 2064                        // 1024+8 halves, bytes
static constexpr int PK_OFF_ST = 64 * WH_STRIDE;              // 132096
static constexpr int PK_STAGE = 32 * PK_ROWB;                 // 33280
static constexpr int PK_OFF_AT = PK_OFF_ST + 2 * PK_STAGE;    // 198656
static constexpr int PK_AT_ROWB = 272;                        // 64 floats + pad
static constexpr int PK_AT_BUF = 32 * PK_AT_ROWB;             // 8704
static constexpr int PK_SMEM = PK_OFF_AT + 2 * PK_AT_BUF;     // 216064

__device__ __forceinline__ void pk_prefetch(
    uint32_t stageBase, const fp16* hh, int m0, int chunk, int tid) {
    const int koff = chunk * PK_KC;
#pragma unroll
    for (int j = 0; j < 16; j++) {
        int u = tid + j * 128;
        int r = u >> 6, q = u & 63;
        cpasync16(stageBase + (uint32_t)(r * PK_ROWB + q * 16),
                  hh + (size_t)(m0 + r) * HH + koff + q * 8);
    }
}

__device__ __forceinline__ void pk_prefetch_A(
    uint32_t sb, const float* A, int t, int m0, int n0, int tid) {
    const uint32_t abuf = sb + PK_OFF_AT + (uint32_t)((t & 1) * PK_AT_BUF);
#pragma unroll
    for (int j = 0; j < 4; j++) {
        int u = tid + j * 128;
        int r = u >> 4, q = u & 15;
        cpasync16(abuf + (uint32_t)(r * PK_AT_ROWB + q * 16),
                  A + ((size_t)t * BB + m0 + r) * HH + n0 + q * 4);
    }
}

__global__ __launch_bounds__(128) void step_persistent(
    const fp16* __restrict__ Whhi, const float* __restrict__ A,
    fp16* __restrict__ hhiB,            // [2][BB*HH]
    fp16* __restrict__ hloT,            // lo of final h (for GEMM3)
    float* __restrict__ hT_out) {
    extern __shared__ __align__(16) char smem[];
    const uint32_t sb = smem_to_u32(smem);
    const int tid = threadIdx.x;
    const int wid = tid >> 5, lane = tid & 31;
    const int warpM = wid & 1, warpN = wid >> 1;   // 2 x 2: warp tile 16 x 32
    const int grp = blockIdx.x & 7;
    const int m0 = grp * 32;
    const int n0 = (blockIdx.x >> 3) * 64;

    // one-time: W_h-hi tile -> persistent smem (64 rows x 2048B, stride 2064)
    for (int u = tid; u < 64 * 128; u += 128) {
        int r = u >> 7, q = u & 127;
        cpasync16(sb + (uint32_t)(r * WH_STRIDE + q * 16),
                  Whhi + (size_t)(n0 + r) * HH + q * 8);
    }
    CP_COMMIT();
    CP_WAIT0();
    __syncthreads();

    const int aRow = warpM * 16 + (lane & 15);
    const int aColB = (lane >> 4) * 16;
    const int bRowL = (lane & 7) + ((lane >> 4) << 3);
    const int bColB = ((lane >> 3) & 1) * 16;

    // A_0 into buffer 0 (its own commit group)
    pk_prefetch_A(sb, A, 0, m0, n0, tid);
    CP_COMMIT();

    for (int t = 0; t < TT; t++) {
        const int ib = t & 1, ob = ib ^ 1;
        const fp16* hh = hhiB + (size_t)ib * BB * HH;
        fp16* ohh = hhiB + (size_t)ob * BB * HH;

        float acc[4][4];
#pragma unroll
        for (int b = 0; b < 4; b++)
#pragma unroll
            for (int c = 0; c < 4; c++) acc[b][c] = 0.0f;

        // h chunk0, then chunk1 (separate commit groups)
        pk_prefetch(sb + PK_OFF_ST, hh, m0, 0, tid);
        CP_COMMIT();
        pk_prefetch(sb + PK_OFF_ST + PK_STAGE, hh, m0, 1, tid);
        CP_COMMIT();

        // pending: A(t), c0, c1 -> wait1 completes A(t)+c0
        CP_WAIT1();
        __syncthreads();
#pragma unroll
        for (int i = 0; i < 2; i++) {                // 2 chunks of K=512
            const uint32_t s0 = sb + PK_OFF_ST + i * PK_STAGE;
#pragma unroll
            for (int ks = 0; ks < PK_KC / 16; ks++) {   // 32 K16-steps
                const int kB = ks * 32;
                uint32_t Ahf[4], Bh[2][4];
                ldsm4(Ahf, s0 + (uint32_t)(aRow * PK_ROWB + kB + aColB));
#pragma unroll
                for (int nt = 0; nt < 2; nt++) {
                    const int row = warpN * 32 + nt * 16 + bRowL;
                    ldsm4(Bh[nt],
                          sb + (uint32_t)(row * WH_STRIDE + i * 1024 + kB + bColB));
                }
#pragma unroll
                for (int nt = 0; nt < 2; nt++) {
                    mma16816(acc[2 * nt + 0], Ahf, &Bh[nt][0]);
                    mma16816(acc[2 * nt + 1], Ahf, &Bh[nt][2]);
                }
            }
            if (i == 0) {
                CP_WAIT0();        // chunk1 landed
                __syncthreads();   // visible + stage0 reusable next step
            }
        }

        // epilogue: A_t from smem buf (t&1), tanh.approx, write h hi
        const uint32_t abuf = sb + PK_OFF_AT + (uint32_t)((t & 1) * PK_AT_BUF);
        const int mL = warpM * 16 + (lane >> 2);
        const int nLb = warpN * 32 + 2 * (lane & 3);
#pragma unroll
        for (int n8 = 0; n8 < 4; n8++) {
            const int nL = nLb + n8 * 8;
#pragma unroll
            for (int hf = 0; hf < 2; hf++) {
                const int mmL = mL + hf * 8;
                float2 bb;
                asm volatile("ld.shared.v2.f32 {%0,%1}, [%2];"
                             : "=f"(bb.x), "=f"(bb.y)
                             : "r"(abuf + (uint32_t)(mmL * PK_AT_ROWB + nL * 4)));
                float v0 = tanh_fast(acc[n8][2 * hf + 0] + bb.x);
                float v1 = tanh_fast(acc[n8][2 * hf + 1] + bb.y);
                const int mm = m0 + mmL;
                const int nn = n0 + nL;
                fp16 h0 = __float2half_rn(v0), h1 = __float2half_rn(v1);
                uint32_t hw = (uint32_t)__half_as_ushort(h0) |
                              ((uint32_t)__half_as_ushort(h1) << 16);
                *(uint32_t*)(ohh + (size_t)mm * HH + nn) = hw;
                if (t == TT - 1) {
                    uint32_t lw = pack_half2((v0 - __half2float(h0)) * SPLIT_SC,
                                             (v1 - __half2float(h1)) * SPLIT_SC);
                    *(uint32_t*)(hloT + (size_t)mm * HH + nn) = lw;
                    *(float2*)(hT_out + (size_t)mm * HH + nn) =
                        make_float2(v0, v1);
                }
            }
        }

        if (t + 1 < TT) {
            // A_{t+1} prefetch BEFORE the barrier: latency hidden by the wait
            pk_prefetch_A(sb, A, t + 1, m0, n0, tid);
            CP_COMMIT();
            // per-m-group barrier (16 CTAs); last arriver releases and skips
            __syncthreads();
            if (tid == 0) {
                unsigned old;
                asm volatile("atom.add.acq_rel.gpu.u32 %0, [%1], 1;"
                             : "=r"(old) : "l"(&g_arriveG[grp]) : "memory");
                if (old == 16u * (unsigned)(t + 1) - 1u) {
                    asm volatile("st.release.gpu.u32 [%0], %1;"
                                 :: "l"(&g_genG[grp]), "r"((unsigned)(t + 1))
                                 : "memory");
                    // releaser: no poll needed (it IS the release)
                } else {
                    unsigned g;
                    do {
                        asm volatile("ld.acquire.gpu.u32 %0, [%1];"
                                     : "=r"(g) : "l"(&g_genG[grp]) : "memory");
                    } while (g < (unsigned)(t + 1));
                }
            }
            __syncthreads();
        }
    }
}

// -------------------- launch ---------------------------------------------------
extern "C" void kernel_launch(void* const* d_in, const int* in_sizes, int n_in,
                              void* d_out, int out_size) {
    const float* inputs = (const float*)d_in[0];
    const float* b_d    = (const float*)d_in[1];
    const float* W_x    = (const float*)d_in[2];
    const float* W_h    = (const float*)d_in[3];
    const float* b_h    = (const float*)d_in[4];
    const float* W_o    = (const float*)d_in[5];
    const float* b_o    = (const float*)d_in[6];
    float* out = (float*)d_out;

    float *coef, *A;
    fp16 *Uhi, *Wxhi, *Whhi, *Wohi, *hhi, *hloT;
    cudaGetSymbolAddress((void**)&coef, g_coefA);
    cudaGetSymbolAddress((void**)&A, g_A);
    cudaGetSymbolAddress((void**)&Uhi, g_Uhi);
    cudaGetSymbolAddress((void**)&Wxhi, g_Wxhi);
    cudaGetSymbolAddress((void**)&Whhi, g_Whhi);
    cudaGetSymbolAddress((void**)&Wohi, g_Wohi);
    cudaGetSymbolAddress((void**)&hhi, g_hhi);
    cudaGetSymbolAddress((void**)&hloT, g_hloT);

    // GEMM1: KCB=128 -> stage (256+64)*272 = 87040, double-buffered
    constexpr int SMEM_BIG   = 2 * (256 + 64) * 272;         // 174080
    constexpr int SMEM_SMALL = 2 * (2 * 32 + 64) * 144;      // 36864 (KCB=64)
    cudaFuncSetAttribute(mma_gemm<256, 64, 8, 1, false, 128>,
                         cudaFuncAttributeMaxDynamicSharedMemorySize, SMEM_BIG);
    cudaFuncSetAttribute(mma_gemm<32, 64, 2, 4, true, 64>,
                         cudaFuncAttributeMaxDynamicSharedMemorySize, SMEM_SMALL);
    cudaFuncSetAttribute(step_persistent,
                         cudaFuncAttributeMaxDynamicSharedMemorySize, PK_SMEM);

    // 1. coefficients + fused weight fp16 conversion
    coef_kernel<<<(IIN + 255) / 256, 256>>>(b_d, coef);
    {
        int pairs = (WX_N + WH_N + WO_N) / 2;
        whalf_all_kernel<<<(pairs + 255) / 256, 256>>>(W_x, W_h, W_o,
                                                       Wxhi, Whhi, Wohi);
    }

    // 2. fractional differencing -> U (fp16 hi only)
    fracconv_kernel<<<(BB * IIN) / 256, 256>>>(inputs, coef, Uhi);

    // 3. A = U @ W_x^T + b_h  (1-term, 256x64 tiles, KCB=128)
    mma_gemm<256, 64, 8, 1, false, 128>
        <<<dim3(HH / 64, (TT * BB) / 256), 256, SMEM_BIG>>>(
            Uhi, nullptr, Wxhi, b_h, A, IIN, HH);

    // 4. recurrence (persistent, pure-fp16 h, releaser-skips-poll barrier)
    cudaMemsetAsync(hhi, 0, (size_t)BB * HH * sizeof(fp16));  // buf0
    reset_kernel<<<1, 1>>>();
    step_persistent<<<PK_CTAS, 128, PK_SMEM>>>(
        Whhi, A, hhi, hloT, out + (size_t)BB * OO);
    // T=512 even -> final h in buf0

    // 5. out = h_T @ W_o^T + b_o  (2-term: final-h hi + lo)
    mma_gemm<32, 64, 2, 4, true, 64>
        <<<dim3(OO / 64, BB / 32), 256, SMEM_SMALL>>>(
            hhi, hloT, Wohi, b_o, out, HH, OO);

    // 6. mem_T = last K input timesteps
    size_t off = (size_t)BB * OO + (size_t)BB * HH;
    if ((size_t)out_size >= off + (size_t)KF * BB * IIN) {
        cudaMemcpyAsync(out + off, inputs + (size_t)(TT - KF) * BB * IIN,
                        (size_t)KF * BB * IIN * sizeof(float),
                        cudaMemcpyDeviceToDevice);
    }
}

// round 16
// speedup vs baseline: 1.0342x; 1.0342x over previous
#include <cuda_runtime.h>
#include <cuda_fp16.h>
#include <stdint.h>
#include <math.h>

// Problem constants
#define TT   512
#define BB   256
#define IIN  512
#define HH   1024
#define OO   512
#define KF   32

#define SPLIT_SC  4096.0f
#define SPLIT_ISC (1.0f / 4096.0f)

typedef __half fp16;

// -------------------- scratch (static __device__, no allocs) -----------------
__device__ __align__(128) float g_coefA[KF * IIN];
__device__ __align__(128) fp16  g_Uhi[(size_t)TT * BB * IIN];
__device__ __align__(128) float g_A[(size_t)TT * BB * HH];
__device__ __align__(128) fp16  g_Wxhi[HH * IIN];
__device__ __align__(128) fp16  g_Whhi[HH * HH];
__device__ __align__(128) fp16  g_Wohi[OO * HH];
__device__ __align__(128) fp16  g_hhi[2][BB * HH];
__device__ __align__(128) fp16  g_hloT[BB * HH];   // lo of FINAL h only (GEMM3)
__device__ unsigned g_arriveG[8];
__device__ unsigned g_genG[8];

// -------------------- PTX helpers (base sm_100-safe) --------------------------
__device__ __forceinline__ uint32_t smem_to_u32(const void* p) {
    uint32_t a;
    asm("{ .reg .u64 t; cvta.to.shared.u64 t, %1; cvt.u32.u64 %0, t; }"
        : "=r"(a) : "l"(p));
    return a;
}
__device__ __forceinline__ void cpasync16(uint32_t s, const void* g) {
    asm volatile("cp.async.cg.shared.global [%0], [%1], 16;" :: "r"(s), "l"(g));
}
#define CP_COMMIT() asm volatile("cp.async.commit_group;" ::: "memory")
#define CP_WAIT1()  asm volatile("cp.async.wait_group 1;" ::: "memory")
#define CP_WAIT0()  asm volatile("cp.async.wait_group 0;" ::: "memory")

__device__ __forceinline__ void ldsm4(uint32_t* r, uint32_t addr) {
    asm volatile(
        "ldmatrix.sync.aligned.m8n8.x4.shared.b16 {%0,%1,%2,%3}, [%4];"
        : "=r"(r[0]), "=r"(r[1]), "=r"(r[2]), "=r"(r[3]) : "r"(addr));
}
__device__ __forceinline__ void mma16816(float* d, const uint32_t* a,
                                         const uint32_t* b) {
    asm volatile(
        "mma.sync.aligned.m16n8k16.row.col.f32.f16.f16.f32 "
        "{%0,%1,%2,%3}, {%4,%5,%6,%7}, {%8,%9}, {%0,%1,%2,%3};"
        : "+f"(d[0]), "+f"(d[1]), "+f"(d[2]), "+f"(d[3])
        : "r"(a[0]), "r"(a[1]), "r"(a[2]), "r"(a[3]), "r"(b[0]), "r"(b[1]));
}
__device__ __forceinline__ uint32_t pack_half2(float a, float b) {
    fp16 h0 = __float2half_rn(a), h1 = __float2half_rn(b);
    return (uint32_t)__half_as_ushort(h0) |
           ((uint32_t)__half_as_ushort(h1) << 16);
}
__device__ __forceinline__ float tanh_fast(float x) {
    float r;
    asm("tanh.approx.f32 %0, %1;" : "=f"(r) : "f"(x));
    return r;
}

// -------------------- small kernels -------------------------------------------
__global__ void reset_kernel() {
#pragma unroll
    for (int i = 0; i < 8; i++) { g_arriveG[i] = 0u; g_genG[i] = 0u; }
}

__global__ void coef_kernel(const float* __restrict__ b_d, float* __restrict__ coef) {
    int i = blockIdx.x * blockDim.x + threadIdx.x;
    if (i >= IIN) return;
    float d = 0.5f / (1.0f + expf(-b_d[i]));
    float p = 1.0f;
    for (int j = 0; j < KF; j++) {
        p *= ((float)j - d) / ((float)j + 1.0f);
        coef[j * IIN + i] = p;
    }
}

// fused fp32 -> fp16 conversion of all three weight matrices (float2 -> half2)
#define WX_N (HH * IIN)
#define WH_N (HH * HH)
#define WO_N (OO * HH)
__global__ void whalf_all_kernel(const float* __restrict__ W_x,
                                 const float* __restrict__ W_h,
                                 const float* __restrict__ W_o,
                                 fp16* __restrict__ Wxhi,
                                 fp16* __restrict__ Whhi,
                                 fp16* __restrict__ Wohi) {
    int p = blockIdx.x * blockDim.x + threadIdx.x;  // pair index
    int i = p * 2;
    const float* src;
    fp16* dst;
    if (i < WX_N) {
        src = W_x + i; dst = Wxhi + i;
    } else if (i < WX_N + WH_N) {
        src = W_h + (i - WX_N); dst = Whhi + (i - WX_N);
    } else if (i < WX_N + WH_N + WO_N) {
        src = W_o + (i - WX_N - WH_N); dst = Wohi + (i - WX_N - WH_N);
    } else {
        return;
    }
    float2 v = *(const float2*)src;
    *(uint32_t*)dst = pack_half2(v.x, v.y);
}

// U[t,b,i] = x[t,b,i] + sum_{j=1..K} pi_j[i]*x[t-j,b,i]; fp16 hi only.
__global__ void fracconv_kernel(const float* __restrict__ x,
                                const float* __restrict__ coef,
                                fp16* __restrict__ Uhi) {
    int idx = blockIdx.x * blockDim.x + threadIdx.x;  // b*I + i
    int i = idx & (IIN - 1);
    float c[KF];
#pragma unroll
    for (int j = 0; j < KF; j++) c[j] = coef[j * IIN + i];
    float w[KF];
#pragma unroll
    for (int j = 0; j < KF; j++) w[j] = 0.0f;

    const float* xp = x + idx;
    const size_t stride = (size_t)BB * IIN;

    for (int t0 = 0; t0 < TT; t0 += KF) {
#pragma unroll
        for (int tt = 0; tt < KF; tt++) {
            float xt = xp[(size_t)(t0 + tt) * stride];
            float u = xt;
#pragma unroll
            for (int j = 1; j <= KF; j++) u += c[j - 1] * w[(tt - j) & (KF - 1)];
            Uhi[(size_t)(t0 + tt) * stride + idx] = __float2half_rn(u);
            w[tt] = xt;
        }
    }
}

// -------------------- batched mma GEMM (templated K-chunk) --------------------
// Yf = sum_k A*B^T + biasC;  acc(AhBh) [+ scaled corr acc(AlBh) if TWO].

template <int BM, int BN, bool TWO, int KCB>
__device__ __forceinline__ void prefetch_chunk(
    uint32_t sb, int stageByte,
    const fp16* gAh, const fp16* gAl, const fp16* gBh, int Kd, int tid) {
    constexpr int ROWB = (KCB + 8) * 2;
    constexpr int UNITS = KCB / 8;            // 16B units per row
    constexpr int OFF_AL = BM * ROWB;
    constexpr int OFF_BH = (TWO ? 2 : 1) * BM * ROWB;
    const size_t rs = (size_t)Kd * 2;
#pragma unroll
    for (int u = tid; u < BM * UNITS; u += 256) {
        int r = u / UNITS, q = u % UNITS;
        uint32_t so = (uint32_t)(r * ROWB + q * 16);
        cpasync16(sb + stageByte + so, (const char*)gAh + (size_t)r * rs + q * 16);
        if (TWO)
            cpasync16(sb + stageByte + OFF_AL + so,
                      (const char*)gAl + (size_t)r * rs + q * 16);
    }
#pragma unroll
    for (int u = tid; u < BN * UNITS; u += 256) {
        int r = u / UNITS, q = u % UNITS;
        uint32_t so = (uint32_t)(r * ROWB + q * 16);
        cpasync16(sb + stageByte + OFF_BH + so, (const char*)gBh + (size_t)r * rs + q * 16);
    }
}

template <int BM, int BN, int WGM, int WGN, bool TWO, int KCB>
__global__ __launch_bounds__(256) void mma_gemm(
    const fp16* __restrict__ Ahi, const fp16* __restrict__ Alo,
    const fp16* __restrict__ Bhi,
    const float* __restrict__ biasC, float* __restrict__ Yf, int Kd, int ldO) {
    static_assert(WGM * WGN == 8, "8 warps");
    constexpr int WM = BM / WGM, WN = BN / WGN;
    constexpr int MT = WM / 16, NT16 = WN / 16;
    constexpr int ROWB = (KCB + 8) * 2;
    constexpr int STAGE = ((TWO ? 2 : 1) * BM + BN) * ROWB;
    constexpr int OFF_AL = BM * ROWB;
    constexpr int OFF_BH = (TWO ? 2 : 1) * BM * ROWB;

    extern __shared__ __align__(16) char smem[];
    const uint32_t sb = smem_to_u32(smem);
    const int tid = threadIdx.x;
    const int wid = tid >> 5, lane = tid & 31;
    const int warpM = wid % WGM, warpN = wid / WGM;
    const int m0 = blockIdx.y * BM;
    const int n0 = blockIdx.x * BN;

    float acc[MT][NT16 * 2][4];
    float accC[TWO ? MT : 1][TWO ? NT16 * 2 : 1][4];
#pragma unroll
    for (int a = 0; a < MT; a++)
#pragma unroll
        for (int b = 0; b < NT16 * 2; b++)
#pragma unroll
            for (int c = 0; c < 4; c++) acc[a][b][c] = 0.0f;
    if (TWO) {
#pragma unroll
        for (int a = 0; a < MT; a++)
#pragma unroll
            for (int b = 0; b < NT16 * 2; b++)
#pragma unroll
                for (int c = 0; c < 4; c++) accC[a][b][c] = 0.0f;
    }

    const fp16* gAh = Ahi + (size_t)m0 * Kd;
    const fp16* gAl = TWO ? (Alo + (size_t)m0 * Kd) : nullptr;
    const fp16* gBh = Bhi + (size_t)n0 * Kd;

    const int nch = Kd / KCB;
    prefetch_chunk<BM, BN, TWO, KCB>(sb, 0, gAh, gAl, gBh, Kd, tid);
    CP_COMMIT();

    const int aRow = warpM * WM + (lane & 15);
    const int aCol = (lane >> 4) * 16;
    const int bRow = warpN * WN + (lane & 7) + ((lane >> 4) << 3);
    const int bCol = ((lane >> 3) & 1) * 16;

    for (int i = 0; i < nch; i++) {
        const int buf = i & 1;
        if (i + 1 < nch) {
            prefetch_chunk<BM, BN, TWO, KCB>(sb, (buf ^ 1) * STAGE,
                                             gAh + (size_t)(i + 1) * KCB,
                                             TWO ? gAl + (size_t)(i + 1) * KCB : nullptr,
                                             gBh + (size_t)(i + 1) * KCB, Kd, tid);
            CP_COMMIT();
            CP_WAIT1();
        } else {
            CP_WAIT0();
        }
        __syncthreads();

        const uint32_t s0 = sb + buf * STAGE;
#pragma unroll
        for (int ks = 0; ks < KCB / 16; ks++) {
            const int kB = ks * 32;
            uint32_t Ah[MT][4], Al[MT][4], Bh[NT16][4];
#pragma unroll
            for (int mt = 0; mt < MT; mt++) {
                uint32_t ad = s0 + (uint32_t)((aRow + mt * 16) * ROWB + kB + aCol);
                ldsm4(Ah[mt], ad);
                if (TWO) ldsm4(Al[mt], ad + OFF_AL);
            }
#pragma unroll
            for (int nt = 0; nt < NT16; nt++) {
                uint32_t bd = s0 + (uint32_t)((bRow + nt * 16) * ROWB + kB + bCol);
                ldsm4(Bh[nt], bd + OFF_BH);
            }
#pragma unroll
            for (int mt = 0; mt < MT; mt++)
#pragma unroll
                for (int nt = 0; nt < NT16; nt++) {
                    mma16816(acc[mt][2 * nt + 0],  Ah[mt], &Bh[nt][0]);
                    mma16816(acc[mt][2 * nt + 1],  Ah[mt], &Bh[nt][2]);
                    if (TWO) {
                        mma16816(accC[mt][2 * nt + 0], Al[mt], &Bh[nt][0]);
                        mma16816(accC[mt][2 * nt + 1], Al[mt], &Bh[nt][2]);
                    }
                }
        }
        __syncthreads();
    }

#pragma unroll
    for (int mt = 0; mt < MT; mt++) {
#pragma unroll
        for (int nt8 = 0; nt8 < NT16 * 2; nt8++) {
            const int m = m0 + warpM * WM + mt * 16 + (lane >> 2);
            const int n = n0 + warpN * WN + nt8 * 8 + 2 * (lane & 3);
#pragma unroll
            for (int half = 0; half < 2; half++) {
                const int mm = m + half * 8;
                const float2 bb = *(const float2*)(biasC + n);
                float v0 = acc[mt][nt8][2 * half + 0] + bb.x;
                float v1 = acc[mt][nt8][2 * half + 1] + bb.y;
                if (TWO) {
                    v0 += accC[mt][nt8][2 * half + 0] * SPLIT_ISC;
                    v1 += accC[mt][nt8][2 * half + 1] * SPLIT_ISC;
                }
                *(float2*)(Yf + (size_t)mm * ldO + n) = make_float2(v0, v1);
            }
        }
    }
}

// -------------------- persistent recurrence kernel ----------------------------
// R13 structure + releaser-skips-poll barrier (kept from R15).
#define PK_CTAS 128
#define PK_KC   512
#define PK_ROWB 1040                          // (512+8) halves, bytes
#define WH_STRIDE 2064                        // 1024+8 halves, bytes
static constexpr int PK_OFF_ST = 64 * WH_STRIDE;              // 132096
static constexpr int PK_STAGE = 32 * PK_ROWB;                 // 33280
static constexpr int PK_OFF_AT = PK_OFF_ST + 2 * PK_STAGE;    // 198656
static constexpr int PK_AT_ROWB = 272;                        // 64 floats + pad
static constexpr int PK_AT_BUF = 32 * PK_AT_ROWB;             // 8704
static constexpr int PK_SMEM = PK_OFF_AT + 2 * PK_AT_BUF;     // 216064

__device__ __forceinline__ void pk_prefetch(
    uint32_t stageBase, const fp16* hh, int m0, int chunk, int tid) {
    const int koff = chunk * PK_KC;
#pragma unroll
    for (int j = 0; j < 16; j++) {
        int u = tid + j * 128;
        int r = u >> 6, q = u & 63;
        cpasync16(stageBase + (uint32_t)(r * PK_ROWB + q * 16),
                  hh + (size_t)(m0 + r) * HH + koff + q * 8);
    }
}

__device__ __forceinline__ void pk_prefetch_A(
    uint32_t sb, const float* A, int t, int m0, int n0, int tid) {
    const uint32_t abuf = sb + PK_OFF_AT + (uint32_t)((t & 1) * PK_AT_BUF);
#pragma unroll
    for (int j = 0; j < 4; j++) {
        int u = tid + j * 128;
        int r = u >> 4, q = u & 15;
        cpasync16(abuf + (uint32_t)(r * PK_AT_ROWB + q * 16),
                  A + ((size_t)t * BB + m0 + r) * HH + n0 + q * 4);
    }
}

__global__ __launch_bounds__(128) void step_persistent(
    const fp16* __restrict__ Whhi, const float* __restrict__ A,
    fp16* __restrict__ hhiB,            // [2][BB*HH]
    fp16* __restrict__ hloT,            // lo of final h (for GEMM3)
    float* __restrict__ hT_out) {
    extern __shared__ __align__(16) char smem[];
    const uint32_t sb = smem_to_u32(smem);
    const int tid = threadIdx.x;
    const int wid = tid >> 5, lane = tid & 31;
    const int warpM = wid & 1, warpN = wid >> 1;   // 2 x 2: warp tile 16 x 32
    const int grp = blockIdx.x & 7;
    const int m0 = grp * 32;
    const int n0 = (blockIdx.x >> 3) * 64;

    // one-time: W_h-hi tile -> persistent smem (64 rows x 2048B, stride 2064)
    for (int u = tid; u < 64 * 128; u += 128) {
        int r = u >> 7, q = u & 127;
        cpasync16(sb + (uint32_t)(r * WH_STRIDE + q * 16),
                  Whhi + (size_t)(n0 + r) * HH + q * 8);
    }
    CP_COMMIT();
    CP_WAIT0();
    __syncthreads();

    const int aRow = warpM * 16 + (lane & 15);
    const int aColB = (lane >> 4) * 16;
    const int bRowL = (lane & 7) + ((lane >> 4) << 3);
    const int bColB = ((lane >> 3) & 1) * 16;

    // A_0 into buffer 0 (its own commit group)
    pk_prefetch_A(sb, A, 0, m0, n0, tid);
    CP_COMMIT();

    for (int t = 0; t < TT; t++) {
        const int ib = t & 1, ob = ib ^ 1;
        const fp16* hh = hhiB + (size_t)ib * BB * HH;
        fp16* ohh = hhiB + (size_t)ob * BB * HH;

        float acc[4][4];
#pragma unroll
        for (int b = 0; b < 4; b++)
#pragma unroll
            for (int c = 0; c < 4; c++) acc[b][c] = 0.0f;

        // h chunk0, then chunk1 (separate commit groups)
        pk_prefetch(sb + PK_OFF_ST, hh, m0, 0, tid);
        CP_COMMIT();
        pk_prefetch(sb + PK_OFF_ST + PK_STAGE, hh, m0, 1, tid);
        CP_COMMIT();

        // pending: A(t), c0, c1 -> wait1 completes A(t)+c0
        CP_WAIT1();
        __syncthreads();
#pragma unroll
        for (int i = 0; i < 2; i++) {                // 2 chunks of K=512
            const uint32_t s0 = sb + PK_OFF_ST + i * PK_STAGE;
#pragma unroll
            for (int ks = 0; ks < PK_KC / 16; ks++) {   // 32 K16-steps
                const int kB = ks * 32;
                uint32_t Ahf[4], Bh[2][4];
                ldsm4(Ahf, s0 + (uint32_t)(aRow * PK_ROWB + kB + aColB));
#pragma unroll
                for (int nt = 0; nt < 2; nt++) {
                    const int row = warpN * 32 + nt * 16 + bRowL;
                    ldsm4(Bh[nt],
                          sb + (uint32_t)(row * WH_STRIDE + i * 1024 + kB + bColB));
                }
#pragma unroll
                for (int nt = 0; nt < 2; nt++) {
                    mma16816(acc[2 * nt + 0], Ahf, &Bh[nt][0]);
                    mma16816(acc[2 * nt + 1], Ahf, &Bh[nt][2]);
                }
            }
            if (i == 0) {
                CP_WAIT0();        // chunk1 landed
                __syncthreads();   // visible + stage0 reusable next step
            }
        }

        // epilogue: A_t from smem buf (t&1), tanh.approx, write h hi
        const uint32_t abuf = sb + PK_OFF_AT + (uint32_t)((t & 1) * PK_AT_BUF);
        const int mL = warpM * 16 + (lane >> 2);
        const int nLb = warpN * 32 + 2 * (lane & 3);
#pragma unroll
        for (int n8 = 0; n8 < 4; n8++) {
            const int nL = nLb + n8 * 8;
#pragma unroll
            for (int hf = 0; hf < 2; hf++) {
                const int mmL = mL + hf * 8;
                float2 bb;
                asm volatile("ld.shared.v2.f32 {%0,%1}, [%2];"
                             : "=f"(bb.x), "=f"(bb.y)
                             : "r"(abuf + (uint32_t)(mmL * PK_AT_ROWB + nL * 4)));
                float v0 = tanh_fast(acc[n8][2 * hf + 0] + bb.x);
                float v1 = tanh_fast(acc[n8][2 * hf + 1] + bb.y);
                const int mm = m0 + mmL;
                const int nn = n0 + nL;
                fp16 h0 = __float2half_rn(v0), h1 = __float2half_rn(v1);
                uint32_t hw = (uint32_t)__half_as_ushort(h0) |
                              ((uint32_t)__half_as_ushort(h1) << 16);
                *(uint32_t*)(ohh + (size_t)mm * HH + nn) = hw;
                if (t == TT - 1) {
                    uint32_t lw = pack_half2((v0 - __half2float(h0)) * SPLIT_SC,
                                             (v1 - __half2float(h1)) * SPLIT_SC);
                    *(uint32_t*)(hloT + (size_t)mm * HH + nn) = lw;
                    *(float2*)(hT_out + (size_t)mm * HH + nn) =
                        make_float2(v0, v1);
                }
            }
        }

        if (t + 1 < TT) {
            // A_{t+1} prefetch BEFORE the barrier: latency hidden by the wait
            pk_prefetch_A(sb, A, t + 1, m0, n0, tid);
            CP_COMMIT();
            // per-m-group barrier (16 CTAs); last arriver releases and skips
            __syncthreads();
            if (tid == 0) {
                unsigned old;
                asm volatile("atom.add.acq_rel.gpu.u32 %0, [%1], 1;"
                             : "=r"(old) : "l"(&g_arriveG[grp]) : "memory");
                if (old == 16u * (unsigned)(t + 1) - 1u) {
                    asm volatile("st.release.gpu.u32 [%0], %1;"
                                 :: "l"(&g_genG[grp]), "r"((unsigned)(t + 1))
                                 : "memory");
                } else {
                    unsigned g;
                    do {
                        asm volatile("ld.acquire.gpu.u32 %0, [%1];"
                                     : "=r"(g) : "l"(&g_genG[grp]) : "memory");
                    } while (g < (unsigned)(t + 1));
                }
            }
            __syncthreads();
        }
    }
}

// -------------------- launch ---------------------------------------------------
extern "C" void kernel_launch(void* const* d_in, const int* in_sizes, int n_in,
                              void* d_out, int out_size) {
    const float* inputs = (const float*)d_in[0];
    const float* b_d    = (const float*)d_in[1];
    const float* W_x    = (const float*)d_in[2];
    const float* W_h    = (const float*)d_in[3];
    const float* b_h    = (const float*)d_in[4];
    const float* W_o    = (const float*)d_in[5];
    const float* b_o    = (const float*)d_in[6];
    float* out = (float*)d_out;

    float *coef, *A;
    fp16 *Uhi, *Wxhi, *Whhi, *Wohi, *hhi, *hloT;
    cudaGetSymbolAddress((void**)&coef, g_coefA);
    cudaGetSymbolAddress((void**)&A, g_A);
    cudaGetSymbolAddress((void**)&Uhi, g_Uhi);
    cudaGetSymbolAddress((void**)&Wxhi, g_Wxhi);
    cudaGetSymbolAddress((void**)&Whhi, g_Whhi);
    cudaGetSymbolAddress((void**)&Wohi, g_Wohi);
    cudaGetSymbolAddress((void**)&hhi, g_hhi);
    cudaGetSymbolAddress((void**)&hloT, g_hloT);

    // GEMM1: KCB=64 -> stage (256+64)*144 = 46080, x2 = 92160 -> 2 CTAs/SM
    constexpr int SMEM_BIG   = 2 * (256 + 64) * 144;         // 92160
    constexpr int SMEM_SMALL = 2 * (2 * 32 + 64) * 144;      // 36864
    cudaFuncSetAttribute(mma_gemm<256, 64, 8, 1, false, 64>,
                         cudaFuncAttributeMaxDynamicSharedMemorySize, SMEM_BIG);
    cudaFuncSetAttribute(mma_gemm<32, 64, 2, 4, true, 64>,
                         cudaFuncAttributeMaxDynamicSharedMemorySize, SMEM_SMALL);
    cudaFuncSetAttribute(step_persistent,
                         cudaFuncAttributeMaxDynamicSharedMemorySize, PK_SMEM);

    // 1. coefficients + fused weight fp16 conversion
    coef_kernel<<<(IIN + 255) / 256, 256>>>(b_d, coef);
    {
        int pairs = (WX_N + WH_N + WO_N) / 2;
        whalf_all_kernel<<<(pairs + 255) / 256, 256>>>(W_x, W_h, W_o,
                                                       Wxhi, Whhi, Wohi);
    }

    // 2. fractional differencing -> U (fp16 hi only)
    fracconv_kernel<<<(BB * IIN) / 256, 256>>>(inputs, coef, Uhi);

    // 3. A = U @ W_x^T + b_h  (1-term, 256x64 tiles, KCB=64, 2 CTAs/SM)
    mma_gemm<256, 64, 8, 1, false, 64>
        <<<dim3(HH / 64, (TT * BB) / 256), 256, SMEM_BIG>>>(
            Uhi, nullptr, Wxhi, b_h, A, IIN, HH);

    // 4. recurrence (persistent, pure-fp16 h, releaser-skips-poll barrier)
    cudaMemsetAsync(hhi, 0, (size_t)BB * HH * sizeof(fp16));  // buf0
    reset_kernel<<<1, 1>>>();
    step_persistent<<<PK_CTAS, 128, PK_SMEM>>>(
        Whhi, A, hhi, hloT, out + (size_t)BB * OO);
    // T=512 even -> final h in buf0

    // 5. out = h_T @ W_o^T + b_o  (2-term: final-h hi + lo)
    mma_gemm<32, 64, 2, 4, true, 64>
        <<<dim3(OO / 64, BB / 32), 256, SMEM_SMALL>>>(
            hhi, hloT, Wohi, b_o, out, HH, OO);

    // 6. mem_T = last K input timesteps
    size_t off = (size_t)BB * OO + (size_t)BB * HH;
    if ((size_t)out_size >= off + (size_t)KF * BB * IIN) {
        cudaMemcpyAsync(out + off, inputs + (size_t)(TT - KF) * BB * IIN,
                        (size_t)KF * BB * IIN * sizeof(float),
                        cudaMemcpyDeviceToDevice);
    }
}